// round 1
// baseline (speedup 1.0000x reference)
#include <cuda_runtime.h>
#include <math.h>

#define FRAME      480
#define FFT_SIZE   960
#define NHALF      480            // complex FFT length
#define FREQ       481
#define NB_ERB     32
#define NB_DF      96
#define ALPHA_F    0.99f
#define ONE_MINUS_ALPHA 0.01f
#define WNORM_F    (1.0f/960.0f)
#define T_MAX      65536
#define CHUNKS     256
#define PI_F       3.14159265358979f

// ---------------- scratch (static device memory; no allocation) ----------------
__device__ float2 g_tw[608];           // stage twiddles (per (n2,k1), all stages)
__device__ float  g_win[FFT_SIZE];     // vorbis window
__device__ float2 g_rec[FREQ];         // cis(-2*pi*k/960) for real-FFT recombination
__device__ float  g_erb[T_MAX * NB_ERB];     // erb dB values (pre-scan)
__device__ float  g_mag[T_MAX * NB_DF];      // |spec| over first 96 bins
__device__ float  g_carryE[CHUNKS * NB_ERB];
__device__ float  g_inE[CHUNKS * NB_ERB];
__device__ float  g_carryS[CHUNKS * NB_DF];
__device__ float  g_inS[CHUNKS * NB_DF];

// stage metadata: radices {5,4,4,3,2}, M = {480,96,24,6,2}, Mp = M/R = {96,24,6,2,1}
__constant__ int c_stR [5] = {5, 4, 4, 3, 2};
__constant__ int c_stM [5] = {480, 96, 24, 6, 2};
__constant__ int c_stMp[5] = {96, 24, 6, 2, 1};
__constant__ int c_stOf[5] = {0, 480, 576, 600, 606};   // twiddle table offsets

__constant__ int c_bandOff[NB_ERB] =
 {0,2,4,6,8,10,12,14,16,18,20,22,24,26,31,36,43,50,58,68,80,93,108,126,146,170,198,229,266,308,358,414};
__constant__ int c_bandCnt[NB_ERB] =
 {2,2,2,2,2,2,2,2,2,2,2,2,2,5,5,7,7,8,10,12,13,15,18,20,24,28,31,37,42,50,56,67};

// ---------------- helpers ----------------
__device__ __forceinline__ float2 cadd(float2 a, float2 b){ return make_float2(a.x+b.x, a.y+b.y); }
__device__ __forceinline__ float2 csub(float2 a, float2 b){ return make_float2(a.x-b.x, a.y-b.y); }
__device__ __forceinline__ float2 cmul(float2 a, float2 b){ return make_float2(a.x*b.x-a.y*b.y, a.x*b.y+a.y*b.x); }

template<int R> __device__ __forceinline__ void dftR(const float2* v, float2* t);

template<> __device__ __forceinline__ void dftR<2>(const float2* v, float2* t){
    t[0] = cadd(v[0], v[1]);
    t[1] = csub(v[0], v[1]);
}
template<> __device__ __forceinline__ void dftR<3>(const float2* v, float2* t){
    const float2 w1 = make_float2(-0.5f, -0.86602540378f);
    const float2 w2 = make_float2(-0.5f,  0.86602540378f);
    t[0] = cadd(cadd(v[0], v[1]), v[2]);
    t[1] = cadd(v[0], cadd(cmul(v[1], w1), cmul(v[2], w2)));
    t[2] = cadd(v[0], cadd(cmul(v[1], w2), cmul(v[2], w1)));
}
template<> __device__ __forceinline__ void dftR<4>(const float2* v, float2* t){
    float2 e = cadd(v[0], v[2]);
    float2 f = csub(v[0], v[2]);
    float2 g = cadd(v[1], v[3]);
    float2 h = csub(v[1], v[3]);
    t[0] = cadd(e, g);
    t[2] = csub(e, g);
    t[1] = make_float2(f.x + h.y, f.y - h.x);   // f - i*h
    t[3] = make_float2(f.x - h.y, f.y + h.x);   // f + i*h
}
template<> __device__ __forceinline__ void dftR<5>(const float2* v, float2* t){
    const float2 w1 = make_float2( 0.30901699437f, -0.95105651630f);
    const float2 w2 = make_float2(-0.80901699437f, -0.58778525229f);
    const float2 w3 = make_float2(-0.80901699437f,  0.58778525229f);
    const float2 w4 = make_float2( 0.30901699437f,  0.95105651630f);
    t[0] = cadd(cadd(cadd(cadd(v[0],v[1]),v[2]),v[3]),v[4]);
    t[1] = cadd(v[0], cadd(cadd(cmul(v[1],w1), cmul(v[2],w2)), cadd(cmul(v[3],w3), cmul(v[4],w4))));
    t[2] = cadd(v[0], cadd(cadd(cmul(v[1],w2), cmul(v[2],w4)), cadd(cmul(v[3],w1), cmul(v[4],w3))));
    t[3] = cadd(v[0], cadd(cadd(cmul(v[1],w3), cmul(v[2],w1)), cadd(cmul(v[3],w4), cmul(v[4],w2))));
    t[4] = cadd(v[0], cadd(cadd(cmul(v[1],w4), cmul(v[2],w3)), cadd(cmul(v[3],w2), cmul(v[4],w1))));
}

// One Stockham DIF stage: A(read) -> B(write)
template<int R>
__device__ __forceinline__ void do_stage(const float2* __restrict__ A, float2* __restrict__ B,
                                         int L, int Mp, const float2* __restrict__ tw, int tid){
    int items = L * Mp;
    for (int i = tid; i < items; i += 128){
        int a  = i % L;
        int n2 = i / L;
        float2 v[R], o[R];
        #pragma unroll
        for (int r = 0; r < R; r++) v[r] = A[a + L * (r * Mp + n2)];
        dftR<R>(v, o);
        #pragma unroll
        for (int k1 = 0; k1 < R; k1++){
            float2 w = tw[n2 * R + k1];
            B[a + L * (k1 + R * n2)] = cmul(o[k1], w);
        }
    }
    __syncthreads();
}

// ---------------- init tables ----------------
__global__ void init_tables(){
    int tid = blockIdx.x * blockDim.x + threadIdx.x;
    int nth = gridDim.x * blockDim.x;
    // stage twiddles
    for (int idx = tid; idx < 608; idx += nth){
        int s = 0;
        while (s < 4 && idx >= c_stOf[s+1]) s++;
        int rem = idx - c_stOf[s];
        int R = c_stR[s];
        int n2 = rem / R, k1 = rem % R;
        float ang = -2.0f * PI_F * (float)(n2 * k1) / (float)c_stM[s];
        float sv, cv; sincosf(ang, &sv, &cv);
        g_tw[idx] = make_float2(cv, sv);
    }
    // window
    for (int j = tid; j < FFT_SIZE; j += nth){
        float w = sinf(0.5f * PI_F * (j + 0.5f) / 480.0f);
        g_win[j] = sinf(0.5f * PI_F * w * w);
    }
    // recombination twiddles
    for (int k = tid; k < FREQ; k += nth){
        float ang = -PI_F * (float)k / 480.0f;
        float sv, cv; sincosf(ang, &sv, &cv);
        g_rec[k] = make_float2(cv, sv);
    }
}

// ---------------- main FFT + spec + erb(dB) kernel: one block per frame ----------------
__global__ __launch_bounds__(128) void fft_kernel(const float* __restrict__ audio,
                                                  float* __restrict__ out, int T){
    __shared__ float2 sA[NHALF];
    __shared__ float2 sB[NHALF];
    __shared__ float  smag[FREQ];
    int t   = blockIdx.x;
    int tid = threadIdx.x;

    // load + window + pack even/odd into complex
    long base = (long)(t - 1) * FRAME;
    for (int n = tid; n < NHALF; n += 128){
        int j0 = 2*n, j1 = 2*n + 1;
        long i0 = base + j0, i1 = base + j1;
        float x0 = (i0 >= 0) ? audio[i0] : 0.0f;
        float x1 = (i1 >= 0) ? audio[i1] : 0.0f;
        sA[n] = make_float2(x0 * g_win[j0], x1 * g_win[j1]);
    }
    __syncthreads();

    do_stage<5>(sA, sB,   1, 96, g_tw + 0,   tid);
    do_stage<4>(sB, sA,   5, 24, g_tw + 480, tid);
    do_stage<4>(sA, sB,  20,  6, g_tw + 576, tid);
    do_stage<3>(sB, sA,  80,  2, g_tw + 600, tid);
    do_stage<2>(sA, sB, 240,  1, g_tw + 606, tid);
    // result Z[k] in sB (natural order)

    // real-FFT recombination, write spec, stash mag2 / |mag|
    size_t orow = (size_t)t * 962;
    for (int k = tid; k < FREQ; k += 128){
        float2 Zk = sB[(k == NHALF) ? 0 : k];
        int kc = (NHALF - k) % NHALF;
        float2 Zc = sB[kc]; Zc.y = -Zc.y;
        float2 E = make_float2(0.5f*(Zk.x + Zc.x), 0.5f*(Zk.y + Zc.y));
        float2 D = make_float2(Zk.x - Zc.x, Zk.y - Zc.y);
        float2 O = make_float2(0.5f * D.y, -0.5f * D.x);
        float2 X = cadd(E, cmul(g_rec[k], O));
        X.x *= WNORM_F; X.y *= WNORM_F;
        out[orow + 2*k]     = X.x;
        out[orow + 2*k + 1] = X.y;
        float m2 = X.x*X.x + X.y*X.y;
        smag[k] = m2;
        if (k < NB_DF) g_mag[(size_t)t * NB_DF + k] = sqrtf(m2);
    }
    __syncthreads();

    if (tid < NB_ERB){
        int s = c_bandOff[tid], n = c_bandCnt[tid];
        float acc = 0.0f;
        for (int f = 0; f < n; f++) acc += smag[s + f];
        g_erb[(size_t)t * NB_ERB + tid] = 10.0f * log10f(acc / (float)n + 1e-10f);
    }
}

// ---------------- chunked linear-recurrence scans ----------------
__global__ void erb_pass1(int T){
    int w = blockIdx.x * blockDim.x + threadIdx.x;
    if (w >= CHUNKS * NB_ERB) return;
    int ch = w % NB_ERB, c = w / NB_ERB;
    int len = T / CHUNKS;
    const float* x = g_erb + (size_t)c * len * NB_ERB + ch;
    float s = 0.0f;
    for (int i = 0; i < len; i++) s = ALPHA_F * s + ONE_MINUS_ALPHA * x[i * NB_ERB];
    g_carryE[c * NB_ERB + ch] = s;
}

__global__ void spec_pass1(int T){
    int w = blockIdx.x * blockDim.x + threadIdx.x;
    if (w >= CHUNKS * NB_DF) return;
    int ch = w % NB_DF, c = w / NB_DF;
    int len = T / CHUNKS;
    const float* x = g_mag + (size_t)c * len * NB_DF + ch;
    float u = 0.0f;
    for (int i = 0; i < len; i++) u = ALPHA_F * u + ONE_MINUS_ALPHA * x[i * NB_DF];
    g_carryS[c * NB_DF + ch] = u;
}

__global__ void pass2(int T){
    int len = T / CHUNKS;
    float m = powf(ALPHA_F, (float)len);
    int tid = threadIdx.x;
    if (tid < NB_ERB){
        float s = -60.0f - 30.0f * (float)tid / 31.0f;
        for (int c = 0; c < CHUNKS; c++){
            g_inE[c * NB_ERB + tid] = s;
            s = m * s + g_carryE[c * NB_ERB + tid];
        }
    } else if (tid < NB_ERB + NB_DF){
        int ch = tid - NB_ERB;
        float u = 0.001f - 0.0009f * (float)ch / 95.0f;
        for (int c = 0; c < CHUNKS; c++){
            g_inS[c * NB_DF + ch] = u;
            u = m * u + g_carryS[c * NB_DF + ch];
        }
    }
}

__global__ void erb_pass3(float* __restrict__ out, int T){
    int w = blockIdx.x * blockDim.x + threadIdx.x;
    if (w >= CHUNKS * NB_ERB) return;
    int ch = w % NB_ERB, c = w / NB_ERB;
    int len = T / CHUNKS;
    size_t erb_off = (size_t)T * 962;
    const float* x = g_erb + (size_t)c * len * NB_ERB + ch;
    float* o = out + erb_off + (size_t)c * len * NB_ERB + ch;
    float s = g_inE[c * NB_ERB + ch];
    for (int i = 0; i < len; i++){
        float xv = x[i * NB_ERB];
        s = ALPHA_F * s + ONE_MINUS_ALPHA * xv;
        o[i * NB_ERB] = (xv - s) * 0.025f;
    }
}

__global__ void spec_pass3(float* __restrict__ out, int T){
    int w = blockIdx.x * blockDim.x + threadIdx.x;
    if (w >= CHUNKS * NB_DF) return;
    int ch = w % NB_DF, c = w / NB_DF;
    int len = T / CHUNKS;
    size_t sf_off = (size_t)T * 962 + (size_t)T * NB_ERB;
    const float* mg = g_mag + (size_t)c * len * NB_DF + ch;
    const float* sp = out + (size_t)c * len * 962 + 2 * ch;
    float* o = out + sf_off + (size_t)c * len * 192 + 2 * ch;
    float u = g_inS[c * NB_DF + ch];
    for (int i = 0; i < len; i++){
        u = ALPHA_F * u + ONE_MINUS_ALPHA * mg[i * NB_DF];
        float r = rsqrtf(u);
        o[i * 192]     = sp[i * 962]     * r;
        o[i * 192 + 1] = sp[i * 962 + 1] * r;
    }
}

// ---------------- launch ----------------
extern "C" void kernel_launch(void* const* d_in, const int* in_sizes, int n_in,
                              void* d_out, int out_size){
    const float* audio = (const float*)d_in[0];
    float* out = (float*)d_out;
    int T = in_sizes[0] / FRAME;
    if (T > T_MAX) T = T_MAX;

    init_tables<<<8, 256>>>();
    fft_kernel<<<T, 128>>>(audio, out, T);
    erb_pass1 <<<(CHUNKS * NB_ERB + 255) / 256, 256>>>(T);
    spec_pass1<<<(CHUNKS * NB_DF  + 255) / 256, 256>>>(T);
    pass2<<<1, 128>>>(T);
    erb_pass3 <<<(CHUNKS * NB_ERB + 255) / 256, 256>>>(out, T);
    spec_pass3<<<(CHUNKS * NB_DF  + 255) / 256, 256>>>(out, T);
}

// round 2
// speedup vs baseline: 1.2095x; 1.2095x over previous
#include <cuda_runtime.h>
#include <math.h>

#define FRAME      480
#define FFT_SIZE   960
#define NHALF      480
#define FREQ       481
#define NB_ERB     32
#define NB_DF      96
#define ALPHA_F    0.99f
#define ONE_MINUS_ALPHA 0.01f
#define WNORM_F    (1.0f/960.0f)
#define T_MAX      65536
#define CHUNKS     512
#define PI_F       3.14159265358979f

// ---------------- static device scratch ----------------
__device__ float2 g_tw1[480];          // stage1 twiddles: cis(-2pi*n2*k1/480), [n2*10+k1], n2<48
__device__ float2 g_tw2[48];           // stage2 twiddles: cis(-2pi*n2*k1/48),  [n2*8+k1],  n2<6
__device__ float2 g_win2[NHALF];       // window as (w[2j], w[2j+1]) pairs
__device__ float2 g_rec[FREQ];         // cis(-2pi*k/960)
__device__ float  g_erb[T_MAX * NB_ERB];
__device__ float  g_mag[T_MAX * NB_DF];
__device__ float  g_carryE[CHUNKS * NB_ERB];
__device__ float  g_inE[CHUNKS * NB_ERB];
__device__ float  g_carryS[CHUNKS * NB_DF];
__device__ float  g_inS[CHUNKS * NB_DF];

__constant__ int c_bandOff[NB_ERB] =
 {0,2,4,6,8,10,12,14,16,18,20,22,24,26,31,36,43,50,58,68,80,93,108,126,146,170,198,229,266,308,358,414};
__constant__ int c_bandCnt[NB_ERB] =
 {2,2,2,2,2,2,2,2,2,2,2,2,2,5,5,7,7,8,10,12,13,15,18,20,24,28,31,37,42,50,56,67};

// ---------------- complex helpers ----------------
__device__ __forceinline__ float2 cadd(float2 a, float2 b){ return make_float2(a.x+b.x, a.y+b.y); }
__device__ __forceinline__ float2 csub(float2 a, float2 b){ return make_float2(a.x-b.x, a.y-b.y); }
__device__ __forceinline__ float2 cmul(float2 a, float2 b){ return make_float2(a.x*b.x-a.y*b.y, a.x*b.y+a.y*b.x); }

__device__ __forceinline__ void dft3(const float2* v, float2* t){
    const float2 w1 = make_float2(-0.5f, -0.86602540378f);
    const float2 w2 = make_float2(-0.5f,  0.86602540378f);
    t[0] = cadd(cadd(v[0], v[1]), v[2]);
    t[1] = cadd(v[0], cadd(cmul(v[1], w1), cmul(v[2], w2)));
    t[2] = cadd(v[0], cadd(cmul(v[1], w2), cmul(v[2], w1)));
}
__device__ __forceinline__ void dft4(const float2* v, float2* t){
    float2 e = cadd(v[0], v[2]);
    float2 f = csub(v[0], v[2]);
    float2 g = cadd(v[1], v[3]);
    float2 h = csub(v[1], v[3]);
    t[0] = cadd(e, g);
    t[2] = csub(e, g);
    t[1] = make_float2(f.x + h.y, f.y - h.x);
    t[3] = make_float2(f.x - h.y, f.y + h.x);
}
__device__ __forceinline__ void dft5(const float2* v, float2* t){
    const float2 w1 = make_float2( 0.30901699437f, -0.95105651630f);
    const float2 w2 = make_float2(-0.80901699437f, -0.58778525229f);
    const float2 w3 = make_float2(-0.80901699437f,  0.58778525229f);
    const float2 w4 = make_float2( 0.30901699437f,  0.95105651630f);
    t[0] = cadd(cadd(cadd(cadd(v[0],v[1]),v[2]),v[3]),v[4]);
    t[1] = cadd(v[0], cadd(cadd(cmul(v[1],w1), cmul(v[2],w2)), cadd(cmul(v[3],w3), cmul(v[4],w4))));
    t[2] = cadd(v[0], cadd(cadd(cmul(v[1],w2), cmul(v[2],w4)), cadd(cmul(v[3],w1), cmul(v[4],w3))));
    t[3] = cadd(v[0], cadd(cadd(cmul(v[1],w3), cmul(v[2],w1)), cadd(cmul(v[3],w4), cmul(v[4],w2))));
    t[4] = cadd(v[0], cadd(cadd(cmul(v[1],w4), cmul(v[2],w3)), cadd(cmul(v[3],w2), cmul(v[4],w1))));
}
// DIT even/odd composites
__device__ __forceinline__ void dft10(const float2* v, float2* t){
    float2 e[5], o[5], E[5], O[5];
    e[0]=v[0]; e[1]=v[2]; e[2]=v[4]; e[3]=v[6]; e[4]=v[8];
    o[0]=v[1]; o[1]=v[3]; o[2]=v[5]; o[3]=v[7]; o[4]=v[9];
    dft5(e,E); dft5(o,O);
    const float2 w[5] = { make_float2(1.f,0.f),
        make_float2( 0.80901699437f,-0.58778525229f),
        make_float2( 0.30901699437f,-0.95105651630f),
        make_float2(-0.30901699437f,-0.95105651630f),
        make_float2(-0.80901699437f,-0.58778525229f)};
    #pragma unroll
    for (int k=0;k<5;k++){ float2 wo = cmul(O[k], w[k]); t[k]=cadd(E[k],wo); t[k+5]=csub(E[k],wo); }
}
__device__ __forceinline__ void dft8(const float2* v, float2* t){
    float2 e[4], o[4], E[4], O[4];
    e[0]=v[0]; e[1]=v[2]; e[2]=v[4]; e[3]=v[6];
    o[0]=v[1]; o[1]=v[3]; o[2]=v[5]; o[3]=v[7];
    dft4(e,E); dft4(o,O);
    const float2 w[4] = { make_float2(1.f,0.f),
        make_float2( 0.70710678119f,-0.70710678119f),
        make_float2( 0.f,-1.f),
        make_float2(-0.70710678119f,-0.70710678119f)};
    #pragma unroll
    for (int k=0;k<4;k++){ float2 wo = cmul(O[k], w[k]); t[k]=cadd(E[k],wo); t[k+4]=csub(E[k],wo); }
}
__device__ __forceinline__ void dft6(const float2* v, float2* t){
    float2 e[3], o[3], E[3], O[3];
    e[0]=v[0]; e[1]=v[2]; e[2]=v[4];
    o[0]=v[1]; o[1]=v[3]; o[2]=v[5];
    dft3(e,E); dft3(o,O);
    const float2 w[3] = { make_float2(1.f,0.f),
        make_float2( 0.5f,-0.86602540378f),
        make_float2(-0.5f,-0.86602540378f)};
    #pragma unroll
    for (int k=0;k<3;k++){ float2 wo = cmul(O[k], w[k]); t[k]=cadd(E[k],wo); t[k+3]=csub(E[k],wo); }
}

// ---------------- init tables ----------------
__global__ void init_tables(){
    int tid = blockIdx.x * blockDim.x + threadIdx.x;
    int nth = gridDim.x * blockDim.x;
    for (int idx = tid; idx < 480; idx += nth){
        int n2 = idx / 10, k1 = idx % 10;
        float ang = -2.0f * PI_F * (float)(n2 * k1) / 480.0f;
        float sv, cv; sincosf(ang, &sv, &cv);
        g_tw1[idx] = make_float2(cv, sv);
    }
    for (int idx = tid; idx < 48; idx += nth){
        int n2 = idx / 8, k1 = idx % 8;
        float ang = -2.0f * PI_F * (float)(n2 * k1) / 48.0f;
        float sv, cv; sincosf(ang, &sv, &cv);
        g_tw2[idx] = make_float2(cv, sv);
    }
    for (int j = tid; j < NHALF; j += nth){
        float a0 = sinf(0.5f * PI_F * (2*j + 0.5f) / 480.0f);
        float a1 = sinf(0.5f * PI_F * (2*j + 1.5f) / 480.0f);
        g_win2[j] = make_float2(sinf(0.5f * PI_F * a0 * a0), sinf(0.5f * PI_F * a1 * a1));
    }
    for (int k = tid; k < FREQ; k += nth){
        float ang = -PI_F * (float)k / 480.0f;
        float sv, cv; sincosf(ang, &sv, &cv);
        g_rec[k] = make_float2(cv, sv);
    }
}

// ---------------- FFT: 2 frames per 128-thread block, 3 stages ----------------
__global__ __launch_bounds__(128) void fft_kernel(const float* __restrict__ audio,
                                                  float* __restrict__ out, int T){
    __shared__ float2 sA[2][NHALF];
    __shared__ float2 sB[2][NHALF];
    int f  = threadIdx.x >> 6;
    int ft = threadIdx.x & 63;
    int t  = blockIdx.x * 2 + f;
    bool live = (t < T);
    float2* A = sA[f];
    float2* B = sB[f];
    const float2* audio2 = (const float2*)audio;
    long base2 = ((long)t - 1) * (FRAME/2);   // in float2 units

    // stage 1: global -> A   (R=10, L=1, Mp=48), window fused
    if (ft < 48){
        int n2 = ft;
        float2 v[10], o[10];
        #pragma unroll
        for (int r = 0; r < 10; r++){
            long i2 = base2 + (r*48 + n2);
            float2 x = (live && i2 >= 0) ? audio2[i2] : make_float2(0.f,0.f);
            float2 w = g_win2[r*48 + n2];
            v[r] = make_float2(x.x*w.x, x.y*w.y);
        }
        dft10(v, o);
        #pragma unroll
        for (int k1 = 0; k1 < 10; k1++)
            A[k1 + 10*n2] = cmul(o[k1], g_tw1[n2*10 + k1]);
    }
    __syncthreads();

    // stage 2: A -> B  (R=8, L=10, Mp=6)
    if (ft < 60){
        int a = ft % 10, n2 = ft / 10;
        float2 v[8], o[8];
        #pragma unroll
        for (int r = 0; r < 8; r++) v[r] = A[a + 10*(r*6 + n2)];
        dft8(v, o);
        #pragma unroll
        for (int k1 = 0; k1 < 8; k1++)
            B[a + 10*(k1 + 8*n2)] = cmul(o[k1], g_tw2[n2*8 + k1]);
    }
    __syncthreads();

    // stage 3: B -> A  (R=6, L=80, Mp=1), no twiddle
    #pragma unroll
    for (int a = ft; a < 80; a += 64){
        float2 v[6], o[6];
        #pragma unroll
        for (int r = 0; r < 6; r++) v[r] = B[a + 80*r];
        dft6(v, o);
        #pragma unroll
        for (int k1 = 0; k1 < 6; k1++) A[a + 80*k1] = o[k1];
    }
    __syncthreads();

    // recombination -> spec, mag2 into (float*)B
    float* smag = (float*)B;
    float2* out2 = (float2*)out;
    size_t orow = (size_t)t * FREQ;   // NOTE: spec row = 481 float2
    // spec rows are 962 floats = 481 float2, rows are contiguous: row t starts at t*481 float2
    for (int k = ft; k < FREQ; k += 64){
        float2 Zk = A[(k == NHALF) ? 0 : k];
        int kc = (NHALF - k) % NHALF;
        float2 Zc = A[kc]; Zc.y = -Zc.y;
        float2 E = make_float2(0.5f*(Zk.x + Zc.x), 0.5f*(Zk.y + Zc.y));
        float2 D = make_float2(Zk.x - Zc.x, Zk.y - Zc.y);
        float2 O = make_float2(0.5f * D.y, -0.5f * D.x);
        float2 X = cadd(E, cmul(g_rec[k], O));
        X.x *= WNORM_F; X.y *= WNORM_F;
        if (live) out2[orow + k] = X;
        float m2 = X.x*X.x + X.y*X.y;
        smag[k] = m2;
        if (live && k < NB_DF) g_mag[(size_t)t * NB_DF + k] = sqrtf(m2);
    }
    __syncthreads();

    if (live && ft < NB_ERB){
        int s = c_bandOff[ft], n = c_bandCnt[ft];
        float acc = 0.0f;
        for (int q = 0; q < n; q++) acc += smag[s + q];
        g_erb[(size_t)t * NB_ERB + ft] = 10.0f * log10f(acc / (float)n + 1e-10f);
    }
}

// ---------------- chunked linear-recurrence scans ----------------
__global__ void erb_pass1(int T){
    int w = blockIdx.x * blockDim.x + threadIdx.x;
    if (w >= CHUNKS * NB_ERB) return;
    int ch = w % NB_ERB, c = w / NB_ERB;
    int len = T / CHUNKS;
    const float* x = g_erb + (size_t)c * len * NB_ERB + ch;
    float s = 0.0f;
    for (int i = 0; i < len; i++) s = ALPHA_F * s + ONE_MINUS_ALPHA * x[i * NB_ERB];
    g_carryE[c * NB_ERB + ch] = s;
}

__global__ void spec_pass1(int T){
    int w = blockIdx.x * blockDim.x + threadIdx.x;
    if (w >= CHUNKS * NB_DF) return;
    int ch = w % NB_DF, c = w / NB_DF;
    int len = T / CHUNKS;
    const float* x = g_mag + (size_t)c * len * NB_DF + ch;
    float u = 0.0f;
    for (int i = 0; i < len; i++) u = ALPHA_F * u + ONE_MINUS_ALPHA * x[i * NB_DF];
    g_carryS[c * NB_DF + ch] = u;
}

__global__ void pass2(int T){
    int len = T / CHUNKS;
    float m = powf(ALPHA_F, (float)len);
    int tid = threadIdx.x;
    if (tid < NB_ERB){
        float s = -60.0f - 30.0f * (float)tid / 31.0f;
        for (int c = 0; c < CHUNKS; c++){
            g_inE[c * NB_ERB + tid] = s;
            s = m * s + g_carryE[c * NB_ERB + tid];
        }
    } else if (tid < NB_ERB + NB_DF){
        int ch = tid - NB_ERB;
        float u = 0.001f - 0.0009f * (float)ch / 95.0f;
        for (int c = 0; c < CHUNKS; c++){
            g_inS[c * NB_DF + ch] = u;
            u = m * u + g_carryS[c * NB_DF + ch];
        }
    }
}

__global__ void erb_pass3(float* __restrict__ out, int T){
    int w = blockIdx.x * blockDim.x + threadIdx.x;
    if (w >= CHUNKS * NB_ERB) return;
    int ch = w % NB_ERB, c = w / NB_ERB;
    int len = T / CHUNKS;
    size_t erb_off = (size_t)T * 962;
    const float* x = g_erb + (size_t)c * len * NB_ERB + ch;
    float* o = out + erb_off + (size_t)c * len * NB_ERB + ch;
    float s = g_inE[c * NB_ERB + ch];
    for (int i = 0; i < len; i++){
        float xv = x[i * NB_ERB];
        s = ALPHA_F * s + ONE_MINUS_ALPHA * xv;
        o[i * NB_ERB] = (xv - s) * 0.025f;
    }
}

__global__ void spec_pass3(float* __restrict__ out, int T){
    int w = blockIdx.x * blockDim.x + threadIdx.x;
    if (w >= CHUNKS * NB_DF) return;
    int ch = w % NB_DF, c = w / NB_DF;
    int len = T / CHUNKS;
    size_t sf_off = (size_t)T * 962 + (size_t)T * NB_ERB;
    const float* mg = g_mag + (size_t)c * len * NB_DF + ch;
    const float* sp = out + (size_t)c * len * 962 + 2 * ch;
    float* o = out + sf_off + (size_t)c * len * 192 + 2 * ch;
    float u = g_inS[c * NB_DF + ch];
    for (int i = 0; i < len; i++){
        u = ALPHA_F * u + ONE_MINUS_ALPHA * mg[i * NB_DF];
        float r = rsqrtf(u);
        o[i * 192]     = sp[i * 962]     * r;
        o[i * 192 + 1] = sp[i * 962 + 1] * r;
    }
}

// ---------------- launch ----------------
extern "C" void kernel_launch(void* const* d_in, const int* in_sizes, int n_in,
                              void* d_out, int out_size){
    const float* audio = (const float*)d_in[0];
    float* out = (float*)d_out;
    int T = in_sizes[0] / FRAME;
    if (T > T_MAX) T = T_MAX;

    init_tables<<<8, 256>>>();
    fft_kernel<<<(T + 1) / 2, 128>>>(audio, out, T);
    erb_pass1 <<<(CHUNKS * NB_ERB + 255) / 256, 256>>>(T);
    spec_pass1<<<(CHUNKS * NB_DF  + 255) / 256, 256>>>(T);
    pass2<<<1, 128>>>(T);
    erb_pass3 <<<(CHUNKS * NB_ERB + 255) / 256, 256>>>(out, T);
    spec_pass3<<<(CHUNKS * NB_DF  + 255) / 256, 256>>>(out, T);
}